// round 3
// baseline (speedup 1.0000x reference)
#include <cuda_runtime.h>

#define NROI 1024
#define FH   160
#define FW   160
#define CC   256
#define CROPN 14
#define PO   7
#define NPOS 49

// Per-ROI precomputed params: {b, ybase, ystep, xbase, xstep, pad, pad, pad}
// 8 floats = 32 B -> two float4 broadcast loads in the hot kernel.
__device__ float4 g_rp[NROI * 2];

__global__ void roi_prep_kernel(const float* __restrict__ rois,
                                const float* __restrict__ iminfo)
{
    const int i = blockIdx.x * blockDim.x + threadIdx.x;
    if (i >= NROI) return;

    const float rid = rois[i * 5 + 0];
    const float rx1 = rois[i * 5 + 1];
    const float ry1 = rois[i * 5 + 2];
    const float rx2 = rois[i * 5 + 3];
    const float ry2 = rois[i * 5 + 4];
    const float imh = iminfo[i * 2 + 0];
    const float imw = iminfo[i * 2 + 1];

    // Matches reference: y = (y1/imh)*(Hf-1) + iy * ((y2-y1)/imh)*(Hf-1)/(ch-1)
    const float ybase = (ry1 / imh) * (float)(FH - 1);
    const float xbase = (rx1 / imw) * (float)(FW - 1);
    const float ystep = ((ry2 - ry1) / imh) * (float)(FH - 1) / (float)(CROPN - 1);
    const float xstep = ((rx2 - rx1) / imw) * (float)(FW - 1) / (float)(CROPN - 1);

    g_rp[i * 2 + 0] = make_float4(rid, ybase, ystep, xbase);
    g_rp[i * 2 + 1] = make_float4(xstep, 0.0f, 0.0f, 0.0f);
}

__global__ __launch_bounds__(256) void roi_pool_kernel(
    const float* __restrict__ img,
    float* __restrict__ out)
{
    const int blk = blockIdx.x;            // roi * 49 + pooled position
    const int roi = blk / NPOS;
    const int pos = blk - roi * NPOS;
    const int py  = pos / PO;
    const int px  = pos - py * PO;
    const int ch  = threadIdx.x;           // one fp32 channel per thread

    const float4 p0 = __ldg(&g_rp[roi * 2 + 0]);   // broadcast (uniform addr)
    const float4 p1 = __ldg(&g_rp[roi * 2 + 1]);
    const int   b     = (int)p0.x;
    const float ybase = p0.y;
    const float ystep = p0.z;
    const float xbase = p0.w;
    const float xstep = p1.x;

    // channel offset folded into the base pointer
    const float* imgb = img + (size_t)b * (FH * FW * CC) + ch;

    float best = -3.402823466e38f;

    #pragma unroll
    for (int dyi = 0; dyi < 2; ++dyi) {
        const int   iy = 2 * py + dyi;
        const float y  = fmaf((float)iy, ystep, ybase);
        const bool  vy = (y >= 0.0f) && (y <= (float)(FH - 1));
        const float yf = floorf(y);
        const float wy = y - yf;
        const int   yli = (int)fminf(fmaxf(yf,        0.0f), (float)(FH - 1));
        const int   yhi = (int)fminf(fmaxf(yf + 1.0f, 0.0f), (float)(FH - 1));

        const float* rowl = imgb + yli * (FW * CC);
        const float* rowh = imgb + yhi * (FW * CC);

        #pragma unroll
        for (int dxi = 0; dxi < 2; ++dxi) {
            const int   ix = 2 * px + dxi;
            const float x  = fmaf((float)ix, xstep, xbase);
            const bool  vx = (x >= 0.0f) && (x <= (float)(FW - 1));
            const float xf = floorf(x);
            const float wx = x - xf;
            const int   xli = (int)fminf(fmaxf(xf,        0.0f), (float)(FW - 1));
            const int   xhi = (int)fminf(fmaxf(xf + 1.0f, 0.0f), (float)(FW - 1));

            // 4 scalar taps: each warp-LDG is exactly one 128B line (1 wavefront)
            const float tl = __ldg(rowl + xli * CC);
            const float tr = __ldg(rowl + xhi * CC);
            const float bl = __ldg(rowh + xli * CC);
            const float br = __ldg(rowh + xhi * CC);

            const float top = fmaf(tr - tl, wx, tl);
            const float bot = fmaf(br - bl, wx, bl);
            float v = fmaf(bot - top, wy, top);
            if (!(vy && vx)) v = 0.0f;

            best = fmaxf(best, v);
        }
    }

    // streaming store: don't let the 51MB output stream evict the image in L2
    __stcs(out + (size_t)blk * CC + ch, best);
}

extern "C" void kernel_launch(void* const* d_in, const int* in_sizes, int n_in,
                              void* d_out, int out_size)
{
    (void)in_sizes; (void)n_in; (void)out_size;
    const float* img    = (const float*)d_in[0];
    const float* rois   = (const float*)d_in[1];
    const float* iminfo = (const float*)d_in[2];
    float*       out    = (float*)d_out;

    roi_prep_kernel<<<(NROI + 255) / 256, 256>>>(rois, iminfo);
    roi_pool_kernel<<<NROI * NPOS, 256>>>(img, out);
}

// round 4
// speedup vs baseline: 1.7826x; 1.7826x over previous
#include <cuda_runtime.h>

#define NROI 1024
#define NB   8
#define FH   160
#define FW   160
#define CC   256
#define CROPN 14
#define PO   7

// Per-ROI params: {b, ybase, ystep, xbase} / {xstep, -, -, -}
__device__ float4 g_rp[NROI * 2];
__device__ int    g_perm[NROI];

__global__ void roi_prep_kernel(const float* __restrict__ rois,
                                const float* __restrict__ iminfo)
{
    const int i = blockIdx.x * blockDim.x + threadIdx.x;
    if (i >= NROI) return;

    const float rid = rois[i * 5 + 0];
    const float rx1 = rois[i * 5 + 1];
    const float ry1 = rois[i * 5 + 2];
    const float rx2 = rois[i * 5 + 3];
    const float ry2 = rois[i * 5 + 4];
    const float imh = iminfo[i * 2 + 0];
    const float imw = iminfo[i * 2 + 1];

    const float ybase = (ry1 / imh) * (float)(FH - 1);
    const float xbase = (rx1 / imw) * (float)(FW - 1);
    const float ystep = ((ry2 - ry1) / imh) * (float)(FH - 1) / (float)(CROPN - 1);
    const float xstep = ((rx2 - rx1) / imw) * (float)(FW - 1) / (float)(CROPN - 1);

    g_rp[i * 2 + 0] = make_float4(rid, ybase, ystep, xbase);
    g_rp[i * 2 + 1] = make_float4(xstep, 0.0f, 0.0f, 0.0f);
}

// Bucket ROIs by image id so consecutive blocks (≈ concurrent wave) share one
// 26MB image in L2 instead of thrashing all 8 (209MB > 126MB L2).
__global__ void roi_sort_kernel(const float* __restrict__ rois)
{
    __shared__ int cnt[NB];
    __shared__ int off[NB];
    const int i = threadIdx.x;               // 0..1023
    if (i < NB) cnt[i] = 0;
    __syncthreads();
    const int b = (int)rois[i * 5];
    atomicAdd(&cnt[b], 1);
    __syncthreads();
    if (i == 0) {
        int s = 0;
        for (int k = 0; k < NB; ++k) { off[k] = s; s += cnt[k]; }
    }
    __syncthreads();
    const int pos = atomicAdd(&off[b], 1);
    g_perm[pos] = i;
}

// One block per (sorted-roi, pooled-row). 448 threads = 7 px * 64 ch-groups.
__global__ __launch_bounds__(448, 4) void roi_pool_kernel(
    const float* __restrict__ img,
    float* __restrict__ out)
{
    const int blk = blockIdx.x;
    const int sr  = blk / PO;
    const int py  = blk - sr * PO;
    const int roi = g_perm[sr];
    const int px  = threadIdx.x >> 6;        // 0..6
    const int t   = threadIdx.x & 63;        // channel-group (float4)

    const float4 p0 = __ldg(&g_rp[roi * 2 + 0]);
    const float4 p1 = __ldg(&g_rp[roi * 2 + 1]);
    const int   b     = (int)p0.x;
    const float ybase = p0.y;
    const float ystep = p0.z;
    const float xbase = p0.w;
    const float xstep = p1.x;

    const float4* imgb = (const float4*)(img + (size_t)b * (FH * FW * CC)) + t;

    float4 best;
    best.x = best.y = best.z = best.w = -3.402823466e38f;

    #pragma unroll
    for (int dyi = 0; dyi < 2; ++dyi) {
        const int   iy = 2 * py + dyi;
        const float y  = fmaf((float)iy, ystep, ybase);
        const bool  vy = (y >= 0.0f) && (y <= (float)(FH - 1));
        const float yf = floorf(y);
        const float wy = y - yf;
        const int   yli = (int)fminf(fmaxf(yf,        0.0f), (float)(FH - 1));
        const int   yhi = (int)fminf(fmaxf(yf + 1.0f, 0.0f), (float)(FH - 1));

        const float4* rowl = imgb + yli * (FW * CC / 4);
        const float4* rowh = imgb + yhi * (FW * CC / 4);

        #pragma unroll
        for (int dxi = 0; dxi < 2; ++dxi) {
            const int   ix = 2 * px + dxi;
            const float x  = fmaf((float)ix, xstep, xbase);
            const bool  vx = (x >= 0.0f) && (x <= (float)(FW - 1));
            const float xf = floorf(x);
            const float wx = x - xf;
            const int   xli = (int)fminf(fmaxf(xf,        0.0f), (float)(FW - 1));
            const int   xhi = (int)fminf(fmaxf(xf + 1.0f, 0.0f), (float)(FW - 1));

            const float4 tl = __ldg(rowl + xli * (CC / 4));
            const float4 tr = __ldg(rowl + xhi * (CC / 4));
            const float4 bl = __ldg(rowh + xli * (CC / 4));
            const float4 br = __ldg(rowh + xhi * (CC / 4));

            float4 v;
            float top, bot;
            top = fmaf(tr.x - tl.x, wx, tl.x);
            bot = fmaf(br.x - bl.x, wx, bl.x);
            v.x = fmaf(bot - top, wy, top);
            top = fmaf(tr.y - tl.y, wx, tl.y);
            bot = fmaf(br.y - bl.y, wx, bl.y);
            v.y = fmaf(bot - top, wy, top);
            top = fmaf(tr.z - tl.z, wx, tl.z);
            bot = fmaf(br.z - bl.z, wx, bl.z);
            v.z = fmaf(bot - top, wy, top);
            top = fmaf(tr.w - tl.w, wx, tl.w);
            bot = fmaf(br.w - bl.w, wx, bl.w);
            v.w = fmaf(bot - top, wy, top);

            if (!(vy && vx)) { v.x = 0.0f; v.y = 0.0f; v.z = 0.0f; v.w = 0.0f; }

            best.x = fmaxf(best.x, v.x);
            best.y = fmaxf(best.y, v.y);
            best.z = fmaxf(best.z, v.z);
            best.w = fmaxf(best.w, v.w);
        }
    }

    float4* o = (float4*)(out + ((size_t)(roi * PO + py) * PO + px) * CC) + t;
    *o = best;
}

extern "C" void kernel_launch(void* const* d_in, const int* in_sizes, int n_in,
                              void* d_out, int out_size)
{
    (void)in_sizes; (void)n_in; (void)out_size;
    const float* img    = (const float*)d_in[0];
    const float* rois   = (const float*)d_in[1];
    const float* iminfo = (const float*)d_in[2];
    float*       out    = (float*)d_out;

    roi_prep_kernel<<<(NROI + 255) / 256, 256>>>(rois, iminfo);
    roi_sort_kernel<<<1, NROI>>>(rois);
    roi_pool_kernel<<<NROI * PO, 448>>>(img, out);
}

// round 5
// speedup vs baseline: 1.7836x; 1.0006x over previous
#include <cuda_runtime.h>

#define NROI 1024
#define NB   8
#define FH   160
#define FW   160
#define CC   256
#define CROPN 14
#define PO   7

// Per-ROI params: {b, ybase, ystep, xbase} / {xstep, -, -, -}
__device__ float4 g_rp[NROI * 2];
__device__ int    g_perm[NROI];

// Fused setup: per-ROI param precompute + bucket sort by image id, one block.
__global__ __launch_bounds__(NROI) void roi_setup_kernel(
    const float* __restrict__ rois,
    const float* __restrict__ iminfo)
{
    __shared__ int cnt[NB];
    __shared__ int off[NB];
    const int i = threadIdx.x;               // 0..1023, one ROI each

    const float rid = rois[i * 5 + 0];
    const float rx1 = rois[i * 5 + 1];
    const float ry1 = rois[i * 5 + 2];
    const float rx2 = rois[i * 5 + 3];
    const float ry2 = rois[i * 5 + 4];
    const float imh = iminfo[i * 2 + 0];
    const float imw = iminfo[i * 2 + 1];

    const float ybase = (ry1 / imh) * (float)(FH - 1);
    const float xbase = (rx1 / imw) * (float)(FW - 1);
    const float ystep = ((ry2 - ry1) / imh) * (float)(FH - 1) / (float)(CROPN - 1);
    const float xstep = ((rx2 - rx1) / imw) * (float)(FW - 1) / (float)(CROPN - 1);

    g_rp[i * 2 + 0] = make_float4(rid, ybase, ystep, xbase);
    g_rp[i * 2 + 1] = make_float4(xstep, 0.0f, 0.0f, 0.0f);

    // bucket sort by image id -> g_perm (concurrent waves share one image in L2)
    if (i < NB) cnt[i] = 0;
    __syncthreads();
    const int b = (int)rid;
    atomicAdd(&cnt[b], 1);
    __syncthreads();
    if (i == 0) {
        int s = 0;
        for (int k = 0; k < NB; ++k) { off[k] = s; s += cnt[k]; }
    }
    __syncthreads();
    const int pos = atomicAdd(&off[b], 1);
    g_perm[pos] = i;
}

// One block per (sorted-roi, pooled-row). 448 threads = 7 px * 64 ch-groups.
__global__ __launch_bounds__(448, 4) void roi_pool_kernel(
    const float* __restrict__ img,
    float* __restrict__ out)
{
    const int blk = blockIdx.x;
    const int sr  = blk / PO;
    const int py  = blk - sr * PO;
    const int roi = g_perm[sr];
    const int px  = threadIdx.x >> 6;        // 0..6
    const int t   = threadIdx.x & 63;        // channel-group (float4)

    const float4 p0 = __ldg(&g_rp[roi * 2 + 0]);
    const float4 p1 = __ldg(&g_rp[roi * 2 + 1]);
    const int   b     = (int)p0.x;
    const float ybase = p0.y;
    const float ystep = p0.z;
    const float xbase = p0.w;
    const float xstep = p1.x;

    const float4* imgb = (const float4*)(img + (size_t)b * (FH * FW * CC)) + t;

    float4 best;
    best.x = best.y = best.z = best.w = -3.402823466e38f;

    #pragma unroll
    for (int dyi = 0; dyi < 2; ++dyi) {
        const int   iy = 2 * py + dyi;
        const float y  = fmaf((float)iy, ystep, ybase);
        const bool  vy = (y >= 0.0f) && (y <= (float)(FH - 1));
        const float yf = floorf(y);
        const float wy = y - yf;
        const int   yli = (int)fminf(fmaxf(yf,        0.0f), (float)(FH - 1));
        const int   yhi = (int)fminf(fmaxf(yf + 1.0f, 0.0f), (float)(FH - 1));

        const float4* rowl = imgb + yli * (FW * CC / 4);
        const float4* rowh = imgb + yhi * (FW * CC / 4);

        #pragma unroll
        for (int dxi = 0; dxi < 2; ++dxi) {
            const int   ix = 2 * px + dxi;
            const float x  = fmaf((float)ix, xstep, xbase);
            const bool  vx = (x >= 0.0f) && (x <= (float)(FW - 1));
            const float xf = floorf(x);
            const float wx = x - xf;
            const int   xli = (int)fminf(fmaxf(xf,        0.0f), (float)(FW - 1));
            const int   xhi = (int)fminf(fmaxf(xf + 1.0f, 0.0f), (float)(FW - 1));

            const float4 tl = __ldg(rowl + xli * (CC / 4));
            const float4 tr = __ldg(rowl + xhi * (CC / 4));
            const float4 bl = __ldg(rowh + xli * (CC / 4));
            const float4 br = __ldg(rowh + xhi * (CC / 4));

            float4 v;
            float top, bot;
            top = fmaf(tr.x - tl.x, wx, tl.x);
            bot = fmaf(br.x - bl.x, wx, bl.x);
            v.x = fmaf(bot - top, wy, top);
            top = fmaf(tr.y - tl.y, wx, tl.y);
            bot = fmaf(br.y - bl.y, wx, bl.y);
            v.y = fmaf(bot - top, wy, top);
            top = fmaf(tr.z - tl.z, wx, tl.z);
            bot = fmaf(br.z - bl.z, wx, bl.z);
            v.z = fmaf(bot - top, wy, top);
            top = fmaf(tr.w - tl.w, wx, tl.w);
            bot = fmaf(br.w - bl.w, wx, bl.w);
            v.w = fmaf(bot - top, wy, top);

            if (!(vy && vx)) { v.x = 0.0f; v.y = 0.0f; v.z = 0.0f; v.w = 0.0f; }

            best.x = fmaxf(best.x, v.x);
            best.y = fmaxf(best.y, v.y);
            best.z = fmaxf(best.z, v.z);
            best.w = fmaxf(best.w, v.w);
        }
    }

    // streaming store: keep the 51MB output from evicting the image in L2
    float4* o = (float4*)(out + ((size_t)(roi * PO + py) * PO + px) * CC) + t;
    __stcs(o, best);
}

extern "C" void kernel_launch(void* const* d_in, const int* in_sizes, int n_in,
                              void* d_out, int out_size)
{
    (void)in_sizes; (void)n_in; (void)out_size;
    const float* img    = (const float*)d_in[0];
    const float* rois   = (const float*)d_in[1];
    const float* iminfo = (const float*)d_in[2];
    float*       out    = (float*)d_out;

    roi_setup_kernel<<<1, NROI>>>(rois, iminfo);
    roi_pool_kernel<<<NROI * PO, 448>>>(img, out);
}